// round 6
// baseline (speedup 1.0000x reference)
#include <cuda_runtime.h>

// ---------------------------------------------------------------------------
// CrossViewSwapAttention — fp32, f32x2; attention as block-tiled two-GEMM.
//   qf (L=64, Nq=384, d=128), kf/vf (L=64, Nk=480, d=128), heads 4 x dh 32.
// ---------------------------------------------------------------------------

#define NQ_ROWS  24576
#define NK_ROWS  30720
#define D        128

__device__ float g_qp [NQ_ROWS * D];
__device__ float g_kp [NK_ROWS * D];
__device__ float g_vp [NK_ROWS * D];
__device__ float g_att[NQ_ROWS * D];

typedef unsigned long long u64;

__device__ __forceinline__ u64 fma2(u64 a, u64 b, u64 c) {
    u64 d;
    asm("fma.rn.f32x2 %0, %1, %2, %3;" : "=l"(d) : "l"(a), "l"(b), "l"(c));
    return d;
}
__device__ __forceinline__ u64 pack2(float x, float y) {
    u64 d;
    asm("mov.b64 %0, {%1, %2};" : "=l"(d) : "f"(x), "f"(y));
    return d;
}
__device__ __forceinline__ float2 unpack2(u64 v) {
    float2 r;
    asm("mov.b64 {%0, %1}, %2;" : "=f"(r.x), "=f"(r.y) : "l"(v));
    return r;
}
__device__ __forceinline__ float ex2(float x) {
    float r;
    asm("ex2.approx.f32 %0, %1;" : "=f"(r) : "f"(x));
    return r;
}

// ---------------------------------------------------------------------------
// Kernel A: fused LayerNorm + Linear for q,k,v (one launch, 64 rows/block).
// xT stored transposed; stride 66 (2-way STS conflict, 8B-aligned u64 reads).
// ---------------------------------------------------------------------------
#define LN_ROWS 64
#define XT_STRIDE 66

__global__ __launch_bounds__(128)
void ln_all_kernel(const float* __restrict__ q,
                   const float* __restrict__ k,
                   const float* __restrict__ v,
                   const float* __restrict__ lnq_g, const float* __restrict__ lnq_b,
                   const float* __restrict__ Wq,    const float* __restrict__ bq,
                   const float* __restrict__ lnk_g, const float* __restrict__ lnk_b,
                   const float* __restrict__ Wk,    const float* __restrict__ bk,
                   const float* __restrict__ lnv_g, const float* __restrict__ lnv_b,
                   const float* __restrict__ Wv,    const float* __restrict__ bv)
{
    __shared__ float xT[128 * XT_STRIDE];
    const int bx   = blockIdx.x;
    const int tid  = threadIdx.x;
    const int warp = tid >> 5;
    const int lane = tid & 31;

    const float *x, *gamma, *beta, *W, *blin;
    float* out;
    int rowsPerL, perN, rbase;
    if (bx < 384) {
        x = q; gamma = lnq_g; beta = lnq_b; W = Wq; blin = bq;
        out = g_qp; rowsPerL = 384; perN = 64; rbase = bx * LN_ROWS;
    } else if (bx < 864) {
        x = k; gamma = lnk_g; beta = lnk_b; W = Wk; blin = bk;
        out = g_kp; rowsPerL = 480; perN = 80; rbase = (bx - 384) * LN_ROWS;
    } else {
        x = v; gamma = lnv_g; beta = lnv_b; W = Wv; blin = bv;
        out = g_vp; rowsPerL = 480; perN = 80; rbase = (bx - 864) * LN_ROWS;
    }

    const float g0 = gamma[lane],      g1 = gamma[lane + 32],
                g2 = gamma[lane + 64], g3 = gamma[lane + 96];
    const float b0 = beta[lane],       b1 = beta[lane + 32],
                b2 = beta[lane + 64],  b3 = beta[lane + 96];

    #pragma unroll 4
    for (int rr = 0; rr < 16; rr++) {
        const int r   = warp * 16 + rr;
        const int row = rbase + r;
        const int L   = row / rowsPerL;
        const int N   = row - L * rowsPerL;
        const int nn  = N / perN;
        const int wi  = N - nn * perN;
        const float* xr = x + ((nn * 64 + L) * perN + wi) * D;

        const float v0 = xr[lane],      v1 = xr[lane + 32],
                    v2 = xr[lane + 64], v3 = xr[lane + 96];
        float s = v0 + v1 + v2 + v3;
        #pragma unroll
        for (int o = 16; o; o >>= 1) s += __shfl_xor_sync(0xffffffffu, s, o);
        const float mu = s * (1.0f / 128.0f);
        const float d0 = v0 - mu, d1 = v1 - mu, d2 = v2 - mu, d3 = v3 - mu;
        float sq = d0 * d0 + d1 * d1 + d2 * d2 + d3 * d3;
        #pragma unroll
        for (int o = 16; o; o >>= 1) sq += __shfl_xor_sync(0xffffffffu, sq, o);
        const float rstd = rsqrtf(sq * (1.0f / 128.0f) + 1e-5f);

        xT[(lane)      * XT_STRIDE + r] = d0 * rstd * g0 + b0;
        xT[(lane + 32) * XT_STRIDE + r] = d1 * rstd * g1 + b1;
        xT[(lane + 64) * XT_STRIDE + r] = d2 * rstd * g2 + b2;
        xT[(lane + 96) * XT_STRIDE + r] = d3 * rstd * g3 + b3;
    }
    __syncthreads();

    const int rt = tid >> 4;
    const int c8 = (tid & 15) * 8;

    u64 acc2[4][8];
    #pragma unroll
    for (int c = 0; c < 8; c++) {
        const float bb = blin[c8 + c];
        const u64 bb2 = pack2(bb, bb);
        #pragma unroll
        for (int rp = 0; rp < 4; rp++) acc2[rp][c] = bb2;
    }

    const float* xrow = xT + rt * 8;
    #pragma unroll 4
    for (int j = 0; j < 128; j++) {
        const u64* xp = (const u64*)(xrow + j * XT_STRIDE);
        u64 xv[4];
        #pragma unroll
        for (int rp = 0; rp < 4; rp++) xv[rp] = xp[rp];

        const float4* wp = (const float4*)(W + j * 128 + c8);
        const float4 wa = wp[0], wb = wp[1];
        u64 ws[8];
        ws[0] = pack2(wa.x, wa.x); ws[1] = pack2(wa.y, wa.y);
        ws[2] = pack2(wa.z, wa.z); ws[3] = pack2(wa.w, wa.w);
        ws[4] = pack2(wb.x, wb.x); ws[5] = pack2(wb.y, wb.y);
        ws[6] = pack2(wb.z, wb.z); ws[7] = pack2(wb.w, wb.w);

        #pragma unroll
        for (int rp = 0; rp < 4; rp++)
            #pragma unroll
            for (int c = 0; c < 8; c++)
                acc2[rp][c] = fma2(xv[rp], ws[c], acc2[rp][c]);
    }

    #pragma unroll
    for (int rp = 0; rp < 4; rp++) {
        float r0[8], r1[8];
        #pragma unroll
        for (int c = 0; c < 8; c++) {
            const float2 t = unpack2(acc2[rp][c]);
            r0[c] = t.x; r1[c] = t.y;
        }
        float* o0 = out + (rbase + rt * 8 + 2 * rp)     * D + c8;
        float* o1 = out + (rbase + rt * 8 + 2 * rp + 1) * D + c8;
        ((float4*)o0)[0] = make_float4(r0[0], r0[1], r0[2], r0[3]);
        ((float4*)o0)[1] = make_float4(r0[4], r0[5], r0[6], r0[7]);
        ((float4*)o1)[0] = make_float4(r1[0], r1[1], r1[2], r1[3]);
        ((float4*)o1)[1] = make_float4(r1[4], r1[5], r1[6], r1[7]);
    }
}

// ---------------------------------------------------------------------------
// Kernel B: flash attention, block-tiled two-GEMM form.
// Block = (head, L, 64 q-rows). Loop over 10 chunks of 48 keys:
//   S-phase: thread (qg=tid>>3, kg=tid&7) computes 4x6 scores, full dh
//            reduction in-thread (NO shuffles); p stored pre-splatted {p,p}.
//   PV-phase: thread (qg2=tid>>3, cg=tid&7) accumulates 4 rows x 4 dh cols;
//            per key 3 LDS.128 -> 8 fma2, zero MOV splats.
// q pre-scaled by attn_scale * dh^-0.5 * log2e; softmax via bare ex2.
// Static smem exactly 48 KB -> 4 blocks/SM.
// ---------------------------------------------------------------------------
#define KC 48

__global__ __launch_bounds__(128)
void attn_kernel(const float* __restrict__ scale_ptr)
{
    __shared__ u64 qT [16][66];   // [dimpair][qrow]   8448 B
    __shared__ u64 kT [16][50];   // [dimpair][key]    6400 B
    __shared__ u64 vS [48][18];   // [key][dimpair]    6912 B
    __shared__ u64 PT2[48][66];   // [key][qrow] {p,p} 25344 B
    __shared__ float rs_s[8][64]; // [kgroup][qrow]    2048 B   => 49152 total

    const int bx  = blockIdx.x;
    const int h   = bx & 3;
    const int l   = (bx >> 2) & 63;
    const int qt  = bx >> 8;          // 0..5
    const int tid = threadIdx.x;

    const float coef = scale_ptr[0] * 0.17677669529663687f * 1.4426950408889634f;

    const float* qbase = g_qp + (l * 384 + qt * 64) * D + h * 32;
    const float* kbase = g_kp + (l * 480) * D + h * 32;
    const float* vbase = g_vp + (l * 480) * D + h * 32;

    // Stage Q (64 rows x 32 dims), transposed + pre-scaled. 512 float4s.
    #pragma unroll
    for (int t = 0; t < 4; t++) {
        const int i  = tid + t * 128;
        const int r  = i >> 3;
        const int dq = i & 7;
        const float4 f = *(const float4*)(qbase + r * D + dq * 4);
        qT[dq * 2][r]     = pack2(f.x * coef, f.y * coef);
        qT[dq * 2 + 1][r] = pack2(f.z * coef, f.w * coef);
    }

    const int qg = tid >> 3;   // 0..15 (4 rows each)
    const int kg = tid & 7;    // 0..7  (6 keys each)

    float rs[4] = {0.f, 0.f, 0.f, 0.f};
    u64 o[4][2];               // [row][dh colpair]
    #pragma unroll
    for (int i = 0; i < 4; i++) { o[i][0] = 0ULL; o[i][1] = 0ULL; }

    for (int c0 = 0; c0 < 480; c0 += KC) {
        __syncthreads();   // prior PV done before overwriting kT/vS

        // Stage K (transposed) and V (row-major). 384 float4s each.
        #pragma unroll
        for (int t = 0; t < 3; t++) {
            const int i  = tid + t * 128;
            const int r  = i >> 3;
            const int dq = i & 7;
            const float4 fk = *(const float4*)(kbase + (c0 + r) * D + dq * 4);
            kT[dq * 2][r]     = pack2(fk.x, fk.y);
            kT[dq * 2 + 1][r] = pack2(fk.z, fk.w);
            const float4 fv = *(const float4*)(vbase + (c0 + r) * D + dq * 4);
            vS[r][dq * 2]     = pack2(fv.x, fv.y);
            vS[r][dq * 2 + 1] = pack2(fv.z, fv.w);
        }
        __syncthreads();

        // S-phase: 4x6 score tile, dh reduced in-thread.
        u64 s2[4][6];
        #pragma unroll
        for (int i = 0; i < 4; i++)
            #pragma unroll
            for (int j = 0; j < 6; j++) s2[i][j] = 0ULL;

        #pragma unroll 2
        for (int d = 0; d < 16; d++) {
            u64 qv[4], kv[6];
            #pragma unroll
            for (int i = 0; i < 4; i++) qv[i] = qT[d][qg * 4 + i];
            #pragma unroll
            for (int j = 0; j < 6; j++) kv[j] = kT[d][kg * 6 + j];
            #pragma unroll
            for (int i = 0; i < 4; i++)
                #pragma unroll
                for (int j = 0; j < 6; j++)
                    s2[i][j] = fma2(qv[i], kv[j], s2[i][j]);
        }

        #pragma unroll
        for (int j = 0; j < 6; j++) {
            #pragma unroll
            for (int i = 0; i < 4; i++) {
                const float2 t = unpack2(s2[i][j]);
                const float p = ex2(t.x + t.y);
                rs[i] += p;
                PT2[kg * 6 + j][qg * 4 + i] = pack2(p, p);
            }
        }
        __syncthreads();

        // PV-phase: rows qg*4..+4, dh cols cg*4..+4 (colpairs cg*2..+2).
        const int cg = kg;     // same decomposition, renamed for clarity
        #pragma unroll 4
        for (int kk = 0; kk < KC; kk++) {
            u64 p0 = PT2[kk][qg * 4 + 0];
            u64 p1 = PT2[kk][qg * 4 + 1];
            u64 p2 = PT2[kk][qg * 4 + 2];
            u64 p3 = PT2[kk][qg * 4 + 3];
            const u64 v0 = vS[kk][cg * 2];
            const u64 v1 = vS[kk][cg * 2 + 1];
            o[0][0] = fma2(p0, v0, o[0][0]); o[0][1] = fma2(p0, v1, o[0][1]);
            o[1][0] = fma2(p1, v0, o[1][0]); o[1][1] = fma2(p1, v1, o[1][1]);
            o[2][0] = fma2(p2, v0, o[2][0]); o[2][1] = fma2(p2, v1, o[2][1]);
            o[3][0] = fma2(p3, v0, o[3][0]); o[3][1] = fma2(p3, v1, o[3][1]);
        }
    }

    // Row-sum reduction across the 8 k-groups.
    #pragma unroll
    for (int i = 0; i < 4; i++) rs_s[kg][qg * 4 + i] = rs[i];
    __syncthreads();

    #pragma unroll
    for (int i = 0; i < 4; i++) {
        float tot = 0.f;
        #pragma unroll
        for (int g = 0; g < 8; g++) tot += rs_s[g][qg * 4 + i];
        const float inv = 1.0f / tot;
        const float2 a = unpack2(o[i][0]);
        const float2 b = unpack2(o[i][1]);
        float* op = g_att + (l * 384 + qt * 64 + qg * 4 + i) * D + h * 32 + kg * 4;
        *(float4*)op = make_float4(a.x * inv, a.y * inv, b.x * inv, b.y * inv);
    }
}

// ---------------------------------------------------------------------------
// Kernel C: mean over n (commutes with affine proj) + Wp + bp + skip.
// ---------------------------------------------------------------------------
__global__ __launch_bounds__(128)
void proj_kernel(const float* __restrict__ Wp,
                 const float* __restrict__ bp,
                 const float* __restrict__ skip,
                 float* __restrict__ out)
{
    __shared__ float ab[16][128];
    const int tid   = threadIdx.x;
    const int obase = blockIdx.x * 16;

    #pragma unroll
    for (int r = 0; r < 16; r++) {
        const int o  = obase + r;
        const int L  = o >> 6;
        const int wi = o & 63;
        float s = 0.0f;
        #pragma unroll
        for (int n = 0; n < 6; n++)
            s += g_att[(L * 384 + n * 64 + wi) * D + tid];
        ab[r][tid] = s * (1.0f / 6.0f);
    }
    __syncthreads();

    const int c = tid;
    float acc[16];
    const float bb = bp[c];
    #pragma unroll
    for (int r = 0; r < 16; r++) acc[r] = bb;

    #pragma unroll 4
    for (int j = 0; j < 128; j++) {
        const float w = Wp[j * 128 + c];
        #pragma unroll
        for (int r = 0; r < 16; r++) acc[r] = fmaf(ab[r][j], w, acc[r]);
    }
    #pragma unroll
    for (int r = 0; r < 16; r++) {
        const int o = obase + r;
        out[o * D + c] = acc[r] + skip[o * D + c];
    }
}

// ---------------------------------------------------------------------------
extern "C" void kernel_launch(void* const* d_in, const int* in_sizes, int n_in,
                              void* d_out, int out_size)
{
    const float* q          = (const float*)d_in[0];
    const float* k          = (const float*)d_in[1];
    const float* v          = (const float*)d_in[2];
    const float* skip       = (const float*)d_in[3];
    const float* attn_scale = (const float*)d_in[4];
    const float* lnq_g = (const float*)d_in[5];
    const float* lnq_b = (const float*)d_in[6];
    const float* Wq    = (const float*)d_in[7];
    const float* bq    = (const float*)d_in[8];
    const float* lnk_g = (const float*)d_in[9];
    const float* lnk_b = (const float*)d_in[10];
    const float* Wk    = (const float*)d_in[11];
    const float* bk    = (const float*)d_in[12];
    const float* lnv_g = (const float*)d_in[13];
    const float* lnv_b = (const float*)d_in[14];
    const float* Wv    = (const float*)d_in[15];
    const float* bv    = (const float*)d_in[16];
    const float* Wp    = (const float*)d_in[17];
    const float* bp    = (const float*)d_in[18];
    float* out = (float*)d_out;

    ln_all_kernel<<<1344, 128>>>(q, k, v,
                                 lnq_g, lnq_b, Wq, bq,
                                 lnk_g, lnk_b, Wk, bk,
                                 lnv_g, lnv_b, Wv, bv);

    // 4 heads * 64 L * 6 q-tiles of 64 rows
    attn_kernel<<<1536, 128>>>(attn_scale);

    proj_kernel<<<4096 / 16, 128>>>(Wp, bp, skip, out);
}

// round 9
// speedup vs baseline: 1.1462x; 1.1462x over previous
#include <cuda_runtime.h>

// ---------------------------------------------------------------------------
// CrossViewSwapAttention — fp32, f32x2 FMA-bound design.
//   qf (L=64, Nq=384, d=128), kf/vf (L=64, Nk=480, d=128), heads 4 x dh 32.
// ---------------------------------------------------------------------------

#define NQ_ROWS  24576
#define NK_ROWS  30720
#define D        128

__device__ float g_qp [NQ_ROWS * D];
__device__ float g_kp [NK_ROWS * D];
__device__ float g_vp [NK_ROWS * D];
__device__ float g_att[NQ_ROWS * D];

typedef unsigned long long u64;

__device__ __forceinline__ u64 fma2(u64 a, u64 b, u64 c) {
    u64 d;
    asm("fma.rn.f32x2 %0, %1, %2, %3;" : "=l"(d) : "l"(a), "l"(b), "l"(c));
    return d;
}
__device__ __forceinline__ u64 mul2(u64 a, u64 b) {
    u64 d;
    asm("mul.rn.f32x2 %0, %1, %2;" : "=l"(d) : "l"(a), "l"(b));
    return d;
}
__device__ __forceinline__ u64 pack2(float x, float y) {
    u64 d;
    asm("mov.b64 %0, {%1, %2};" : "=l"(d) : "f"(x), "f"(y));
    return d;
}
__device__ __forceinline__ float2 unpack2(u64 v) {
    float2 r;
    asm("mov.b64 {%0, %1}, %2;" : "=f"(r.x), "=f"(r.y) : "l"(v));
    return r;
}
__device__ __forceinline__ float ex2(float x) {
    float r;
    asm("ex2.approx.f32 %0, %1;" : "=f"(r) : "f"(x));
    return r;
}

// ---------------------------------------------------------------------------
// Kernel A: fused LayerNorm + Linear for q,k,v (one launch, 64 rows/block).
// Phase 2 streams W through a 16 KB SMEM quarter-buffer (4 refills) so the
// inner loop is all-SMEM (no LDG latency in the fma stream).
// Dynamic smem: xT (128 x 66 floats) + W_s (32 x 128 floats) = 50176 B.
// ---------------------------------------------------------------------------
#define LN_ROWS 64
#define XT_STRIDE 66
#define LN_SMEM_BYTES (128 * XT_STRIDE * 4 + 32 * 128 * 4)

__global__ __launch_bounds__(128, 4)
void ln_all_kernel(const float* __restrict__ q,
                   const float* __restrict__ k,
                   const float* __restrict__ v,
                   const float* __restrict__ lnq_g, const float* __restrict__ lnq_b,
                   const float* __restrict__ Wq,    const float* __restrict__ bq,
                   const float* __restrict__ lnk_g, const float* __restrict__ lnk_b,
                   const float* __restrict__ Wk,    const float* __restrict__ bk,
                   const float* __restrict__ lnv_g, const float* __restrict__ lnv_b,
                   const float* __restrict__ Wv,    const float* __restrict__ bv)
{
    extern __shared__ float smem[];
    float* xT  = smem;                       // [j][row], stride 66
    float* W_s = smem + 128 * XT_STRIDE;     // [32][128] current W quarter

    const int bx   = blockIdx.x;
    const int tid  = threadIdx.x;
    const int warp = tid >> 5;
    const int lane = tid & 31;

    const float *x, *gamma, *beta, *W, *blin;
    float* out;
    int rowsPerL, perN, rbase;
    if (bx < 384) {
        x = q; gamma = lnq_g; beta = lnq_b; W = Wq; blin = bq;
        out = g_qp; rowsPerL = 384; perN = 64; rbase = bx * LN_ROWS;
    } else if (bx < 864) {
        x = k; gamma = lnk_g; beta = lnk_b; W = Wk; blin = bk;
        out = g_kp; rowsPerL = 480; perN = 80; rbase = (bx - 384) * LN_ROWS;
    } else {
        x = v; gamma = lnv_g; beta = lnv_b; W = Wv; blin = bv;
        out = g_vp; rowsPerL = 480; perN = 80; rbase = (bx - 864) * LN_ROWS;
    }

    const float g0 = gamma[lane],      g1 = gamma[lane + 32],
                g2 = gamma[lane + 64], g3 = gamma[lane + 96];
    const float b0 = beta[lane],       b1 = beta[lane + 32],
                b2 = beta[lane + 64],  b3 = beta[lane + 96];

    // Phase 1: each warp normalizes 16 rows, stored transposed into xT.
    #pragma unroll 4
    for (int rr = 0; rr < 16; rr++) {
        const int r   = warp * 16 + rr;
        const int row = rbase + r;
        const int L   = row / rowsPerL;
        const int N   = row - L * rowsPerL;
        const int nn  = N / perN;
        const int wi  = N - nn * perN;
        const float* xr = x + ((nn * 64 + L) * perN + wi) * D;

        const float v0 = xr[lane],      v1 = xr[lane + 32],
                    v2 = xr[lane + 64], v3 = xr[lane + 96];
        float s = v0 + v1 + v2 + v3;
        #pragma unroll
        for (int o = 16; o; o >>= 1) s += __shfl_xor_sync(0xffffffffu, s, o);
        const float mu = s * (1.0f / 128.0f);
        const float d0 = v0 - mu, d1 = v1 - mu, d2 = v2 - mu, d3 = v3 - mu;
        float sq = d0 * d0 + d1 * d1 + d2 * d2 + d3 * d3;
        #pragma unroll
        for (int o = 16; o; o >>= 1) sq += __shfl_xor_sync(0xffffffffu, sq, o);
        const float rstd = rsqrtf(sq * (1.0f / 128.0f) + 1e-5f);

        xT[(lane)      * XT_STRIDE + r] = d0 * rstd * g0 + b0;
        xT[(lane + 32) * XT_STRIDE + r] = d1 * rstd * g1 + b1;
        xT[(lane + 64) * XT_STRIDE + r] = d2 * rstd * g2 + b2;
        xT[(lane + 96) * XT_STRIDE + r] = d3 * rstd * g3 + b3;
    }

    // Phase 2: thread (rt, ct) owns row-pairs [rt*8..+8), cols [ct*8..+8).
    const int rt = tid >> 4;
    const int c8 = (tid & 15) * 8;

    u64 acc2[4][8];
    #pragma unroll
    for (int c = 0; c < 8; c++) {
        const float bb = blin[c8 + c];
        const u64 bb2 = pack2(bb, bb);
        #pragma unroll
        for (int rp = 0; rp < 4; rp++) acc2[rp][c] = bb2;
    }

    const float* xrow = xT + rt * 8;

    for (int q4 = 0; q4 < 4; q4++) {
        __syncthreads();   // phase-1 done (first iter) / previous quarter consumed
        // Stage W rows [q4*32, q4*32+32): 4096 floats = 8 float4 per thread.
        {
            const float4* src = (const float4*)(W + q4 * 32 * 128);
            float4* dst = (float4*)W_s;
            #pragma unroll
            for (int t = 0; t < 8; t++) dst[tid + t * 128] = src[tid + t * 128];
        }
        __syncthreads();

        #pragma unroll 4
        for (int jj = 0; jj < 32; jj++) {
            const int j = q4 * 32 + jj;
            const u64* xp = (const u64*)(xrow + j * XT_STRIDE);
            u64 xv[4];
            #pragma unroll
            for (int rp = 0; rp < 4; rp++) xv[rp] = xp[rp];

            const float4* wp = (const float4*)(W_s + jj * 128 + c8);
            const float4 wa = wp[0], wb = wp[1];
            u64 ws[8];
            ws[0] = pack2(wa.x, wa.x); ws[1] = pack2(wa.y, wa.y);
            ws[2] = pack2(wa.z, wa.z); ws[3] = pack2(wa.w, wa.w);
            ws[4] = pack2(wb.x, wb.x); ws[5] = pack2(wb.y, wb.y);
            ws[6] = pack2(wb.z, wb.z); ws[7] = pack2(wb.w, wb.w);

            #pragma unroll
            for (int rp = 0; rp < 4; rp++)
                #pragma unroll
                for (int c = 0; c < 8; c++)
                    acc2[rp][c] = fma2(xv[rp], ws[c], acc2[rp][c]);
        }
    }

    #pragma unroll
    for (int rp = 0; rp < 4; rp++) {
        float r0[8], r1[8];
        #pragma unroll
        for (int c = 0; c < 8; c++) {
            const float2 t = unpack2(acc2[rp][c]);
            r0[c] = t.x; r1[c] = t.y;
        }
        float* o0 = out + (rbase + rt * 8 + 2 * rp)     * D + c8;
        float* o1 = out + (rbase + rt * 8 + 2 * rp + 1) * D + c8;
        ((float4*)o0)[0] = make_float4(r0[0], r0[1], r0[2], r0[3]);
        ((float4*)o0)[1] = make_float4(r0[4], r0[5], r0[6], r0[7]);
        ((float4*)o1)[0] = make_float4(r1[0], r1[1], r1[2], r1[3]);
        ((float4*)o1)[1] = make_float4(r1[4], r1[5], r1[6], r1[7]);
    }
}

// ---------------------------------------------------------------------------
// Kernel B: attention (reverted to the measured-best R5 config).
// Grid 512 = 4h * 64L * 2 q-tiles; thread pair shares 3 q rows; even thread
// dh[0:16), odd dh[16:32); dot halves combined via shfl_xor; bare ex2.
// ---------------------------------------------------------------------------
#define KCHUNK 96

__global__ __launch_bounds__(128, 3)
void attn_kernel(const float* __restrict__ scale_ptr)
{
    __shared__ float4 ks4[KCHUNK * 8];
    __shared__ float4 vs4[KCHUNK * 8];

    const int bx   = blockIdx.x;
    const int h    = bx & 3;
    const int l    = (bx >> 2) & 63;
    const int qt   = bx >> 8;          // 0..1
    const int tid  = threadIdx.x;
    const int pair = tid >> 1;
    const int half = tid & 1;

    const float coef = scale_ptr[0] * 0.17677669529663687f * 1.4426950408889634f;

    u64 qr[3][8];
    #pragma unroll
    for (int r = 0; r < 3; r++) {
        const float4* qp = (const float4*)(g_qp +
            (l * 384 + qt * 192 + pair + r * 64) * D + h * 32 + half * 16);
        #pragma unroll
        for (int i = 0; i < 4; i++) {
            float4 t = qp[i];
            qr[r][2 * i]     = pack2(t.x * coef, t.y * coef);
            qr[r][2 * i + 1] = pack2(t.z * coef, t.w * coef);
        }
    }

    u64 acc[3][8];
    #pragma unroll
    for (int r = 0; r < 3; r++)
        #pragma unroll
        for (int i = 0; i < 8; i++) acc[r][i] = 0ULL;
    float lsum[3] = {0.0f, 0.0f, 0.0f};

    const float* kbase = g_kp + (l * 480) * D + h * 32;
    const float* vbase = g_vp + (l * 480) * D + h * 32;

    for (int c0 = 0; c0 < 480; c0 += KCHUNK) {
        __syncthreads();
        #pragma unroll
        for (int i = 0; i < (KCHUNK * 8) / 128; i++) {
            const int idx = tid + i * 128;
            const int row = idx >> 3;
            const int c4  = idx & 7;
            ks4[idx] = *(const float4*)(kbase + (c0 + row) * D + c4 * 4);
            vs4[idx] = *(const float4*)(vbase + (c0 + row) * D + c4 * 4);
        }
        __syncthreads();

        #pragma unroll 4
        for (int kk = 0; kk < KCHUNK; kk++) {
            const u64* kr = (const u64*)(ks4 + kk * 8 + half * 4);
            u64 kf[8];
            #pragma unroll
            for (int i = 0; i < 8; i++) kf[i] = kr[i];

            float p[3];
            #pragma unroll
            for (int r = 0; r < 3; r++) {
                u64 sa = 0ULL, sb = 0ULL;
                #pragma unroll
                for (int i = 0; i < 4; i++) {
                    sa = fma2(qr[r][2 * i],     kf[2 * i],     sa);
                    sb = fma2(qr[r][2 * i + 1], kf[2 * i + 1], sb);
                }
                const float2 sx = unpack2(sa);
                const float2 sy = unpack2(sb);
                const float hsum = (sx.x + sx.y) + (sy.x + sy.y);
                const float tot = hsum + __shfl_xor_sync(0xffffffffu, hsum, 1);
                p[r] = ex2(tot);
                lsum[r] += p[r];
            }

            const u64* vr = (const u64*)(vs4 + kk * 8 + half * 4);
            u64 vf[8];
            #pragma unroll
            for (int i = 0; i < 8; i++) vf[i] = vr[i];
            #pragma unroll
            for (int r = 0; r < 3; r++) {
                const u64 p2 = pack2(p[r], p[r]);
                #pragma unroll
                for (int i = 0; i < 8; i++) acc[r][i] = fma2(p2, vf[i], acc[r][i]);
            }
        }
    }

    #pragma unroll
    for (int r = 0; r < 3; r++) {
        const float inv = 1.0f / lsum[r];
        const u64 inv2 = pack2(inv, inv);
        u64* op = (u64*)(g_att +
            (l * 384 + qt * 192 + pair + r * 64) * D + h * 32 + half * 16);
        #pragma unroll
        for (int i = 0; i < 8; i++) op[i] = mul2(acc[r][i], inv2);
    }
}

// ---------------------------------------------------------------------------
// Kernel C: mean over n (commutes with affine proj) + Wp + bp + skip.
// ---------------------------------------------------------------------------
__global__ __launch_bounds__(128)
void proj_kernel(const float* __restrict__ Wp,
                 const float* __restrict__ bp,
                 const float* __restrict__ skip,
                 float* __restrict__ out)
{
    __shared__ float ab[16][128];
    const int tid   = threadIdx.x;
    const int obase = blockIdx.x * 16;

    #pragma unroll
    for (int r = 0; r < 16; r++) {
        const int o  = obase + r;
        const int L  = o >> 6;
        const int wi = o & 63;
        float s = 0.0f;
        #pragma unroll
        for (int n = 0; n < 6; n++)
            s += g_att[(L * 384 + n * 64 + wi) * D + tid];
        ab[r][tid] = s * (1.0f / 6.0f);
    }
    __syncthreads();

    const int c = tid;
    float acc[16];
    const float bb = bp[c];
    #pragma unroll
    for (int r = 0; r < 16; r++) acc[r] = bb;

    #pragma unroll 4
    for (int j = 0; j < 128; j++) {
        const float w = Wp[j * 128 + c];
        #pragma unroll
        for (int r = 0; r < 16; r++) acc[r] = fmaf(ab[r][j], w, acc[r]);
    }
    #pragma unroll
    for (int r = 0; r < 16; r++) {
        const int o = obase + r;
        out[o * D + c] = acc[r] + skip[o * D + c];
    }
}

// ---------------------------------------------------------------------------
extern "C" void kernel_launch(void* const* d_in, const int* in_sizes, int n_in,
                              void* d_out, int out_size)
{
    const float* q          = (const float*)d_in[0];
    const float* k          = (const float*)d_in[1];
    const float* v          = (const float*)d_in[2];
    const float* skip       = (const float*)d_in[3];
    const float* attn_scale = (const float*)d_in[4];
    const float* lnq_g = (const float*)d_in[5];
    const float* lnq_b = (const float*)d_in[6];
    const float* Wq    = (const float*)d_in[7];
    const float* bq    = (const float*)d_in[8];
    const float* lnk_g = (const float*)d_in[9];
    const float* lnk_b = (const float*)d_in[10];
    const float* Wk    = (const float*)d_in[11];
    const float* bk    = (const float*)d_in[12];
    const float* lnv_g = (const float*)d_in[13];
    const float* lnv_b = (const float*)d_in[14];
    const float* Wv    = (const float*)d_in[15];
    const float* bv    = (const float*)d_in[16];
    const float* Wp    = (const float*)d_in[17];
    const float* bp    = (const float*)d_in[18];
    float* out = (float*)d_out;

    static int smem_set = 0;
    if (!smem_set) {
        cudaFuncSetAttribute(ln_all_kernel,
                             cudaFuncAttributeMaxDynamicSharedMemorySize,
                             LN_SMEM_BYTES);
        smem_set = 1;
    }

    ln_all_kernel<<<1344, 128, LN_SMEM_BYTES>>>(q, k, v,
                                                lnq_g, lnq_b, Wq, bq,
                                                lnk_g, lnk_b, Wk, bk,
                                                lnv_g, lnv_b, Wv, bv);

    attn_kernel<<<512, 128>>>(attn_scale);

    proj_kernel<<<4096 / 16, 128>>>(Wp, bp, skip, out);
}